// round 13
// baseline (speedup 1.0000x reference)
#include <cuda_runtime.h>
#include <cuda_bf16.h>
#include <cstdint>

typedef unsigned long long u64;

// v scratch: [32768 rows][96 features] fp32, standard order k = ring*32 + ch
__device__ float g_v[32768 * 96];

// ---------------- packed fp32 helpers ----------------
__device__ __forceinline__ u64 fma2(u64 a, u64 b, u64 c) {
    u64 d; asm("fma.rn.f32x2 %0, %1, %2, %3;" : "=l"(d) : "l"(a), "l"(b), "l"(c)); return d;
}
__device__ __forceinline__ u64 pack2(float x, float y) {
    u64 d; asm("mov.b64 %0, {%1, %2};" : "=l"(d) : "r"(__float_as_uint(x)), "r"(__float_as_uint(y))); return d;
}
__device__ __forceinline__ u64 splat2(float x) {
    u64 d; asm("mov.b64 %0, {%1, %1};" : "=l"(d) : "r"(__float_as_uint(x))); return d;
}
__device__ __forceinline__ void unpack2(u64 a, float& x, float& y) {
    unsigned lo, hi; asm("mov.b64 {%0, %1}, %2;" : "=r"(lo), "=r"(hi) : "l"(a));
    x = __uint_as_float(lo); y = __uint_as_float(hi);
}
__device__ __forceinline__ u64 max2(u64 a, u64 b) {
    float a0, a1, b0, b1; unpack2(a, a0, a1); unpack2(b, b0, b1);
    return pack2(fmaxf(a0, b0), fmaxf(a1, b1));
}
__device__ __forceinline__ float lrelu(float x) { return fmaxf(x, 0.2f * x); }

__device__ __forceinline__ void split_pack(float a, float b, uint32_t& hi, uint32_t& lo) {
    __nv_bfloat16 ha = __float2bfloat16(a), hb = __float2bfloat16(b);
    __nv_bfloat16 la = __float2bfloat16(a - __bfloat162float(ha));
    __nv_bfloat16 lb = __float2bfloat16(b - __bfloat162float(hb));
    hi = (uint32_t)__bfloat16_as_ushort(ha) | ((uint32_t)__bfloat16_as_ushort(hb) << 16);
    lo = (uint32_t)__bfloat16_as_ushort(la) | ((uint32_t)__bfloat16_as_ushort(lb) << 16);
}

// ================= Kernel 1: LIFT (unchanged from R12) =================
__global__ __launch_bounds__(256)
void lift_kernel(const float* __restrict__ pgi,
                 const float* __restrict__ W_lift, const float* __restrict__ b_lift)
{
    __shared__ __align__(16) float pts_s[8][1536];
    const int warp = threadIdx.x >> 5, lane = threadIdx.x & 31;
    const int group = blockIdx.x * 8 + warp;          // 0..4095, 8 rows each
    float* pts = pts_s[warp];
    const int ld3 = lane / 3, lm3 = lane - ld3 * 3;

    const u64 ww0 = splat2(__ldg(W_lift + lane));
    const u64 ww1 = splat2(__ldg(W_lift + 32 + lane));
    const u64 ww2 = splat2(__ldg(W_lift + 64 + lane));
    const u64 bbl = splat2(__ldg(b_lift + lane));

    const int grow = group * 8;
    const int b = grow >> 10, g = grow & 1023;
    const int gi = g >> 5, gj = g & 31;
    const float* base = pgi + ((size_t)b * 65536 + (size_t)(gi * 8) * 256 + (size_t)(gj * 8)) * 3;
    if (lane < 24) {
        #pragma unroll
        for (int q = 0; q < 8; q++) {
            const int P = q >> 1, s = q & 1;
            const float* bq = base + q * 24;
            #pragma unroll
            for (int gr = 0; gr < 8; gr++) {
                const float val = __ldcs(bq + (size_t)gr * 768 + lane);
                const int p = gr * 8 + ld3;
                int off;
                if (lm3 == 2) off = 1024 + P * 128 + p * 2 + s;
                else          off = P * 256 + p * 4 + lm3 * 2 + s;
                pts[off] = val;
            }
        }
    }
    __syncwarp();

    #pragma unroll
    for (int P = 0; P < 4; P++) {
        const float* XY = pts + P * 256;
        const float* Z  = pts + 1024 + P * 128;
        u64 mi = pack2(-3.0e38f, -3.0e38f), mt = mi, mo = mi;
        #pragma unroll
        for (int p = 0; p < 64; p += 2) {
            const ulonglong2 xyA = *(const ulonglong2*)(XY + p * 4);
            const ulonglong2 xyB = *(const ulonglong2*)(XY + p * 4 + 4);
            const ulonglong2 zz  = *(const ulonglong2*)(Z + p * 2);
            const u64 hA = fma2(xyA.x, ww0, fma2(xyA.y, ww1, fma2(zz.x, ww2, bbl)));
            const u64 hB = fma2(xyB.x, ww0, fma2(xyB.y, ww1, fma2(zz.y, ww2, bbl)));
            { const int r = p >> 3, c = p & 7, d = min(min(r, c), min(7 - r, 7 - c));
              if (d == 3) mi = max2(mi, hA); else if (d == 2) mt = max2(mt, hA); else mo = max2(mo, hA); }
            { const int r = (p + 1) >> 3, c = (p + 1) & 7, d = min(min(r, c), min(7 - r, 7 - c));
              if (d == 3) mi = max2(mi, hB); else if (d == 2) mt = max2(mt, hB); else mo = max2(mo, hB); }
        }
        const size_t rb = (size_t)(grow + P * 2) * 96;
        float x0, x1;
        unpack2(mi, x0, x1);
        g_v[rb + lane]      = lrelu(x0); g_v[rb + 96 + lane]      = lrelu(x1);
        unpack2(mt, x0, x1);
        g_v[rb + 32 + lane] = lrelu(x0); g_v[rb + 96 + 32 + lane] = lrelu(x1);
        unpack2(mo, x0, x1);
        g_v[rb + 64 + lane] = lrelu(x0); g_v[rb + 96 + 64 + lane] = lrelu(x1);
    }
}

// ================= Kernel 2: MLP via HMMA, ILP-restructured =================
#define K2_THREADS 384
#define NW2 12
#define OFF_B1 1536      // 96 frags * 512B  (W_code 96x128: KT=6, NT=16)
#define OFF_B2 50688     // 64 frags         (W_h1 128x64: KT=8, NT=8)
#define OFF_B3 83456     // 16 frags         (W_h2 64x32:  KT=4, NT=4)
#define OFF_B4 91648     // 4 frags          (W_h3 32x16:  KT=2, NT=2)
#define OFF_VS 93696     // per-warp v stage: 16 rows x 104 floats = 6656B
#define VS_BYTES 6656
#define SMEM2_BYTES (OFF_VS + NW2 * VS_BYTES)   // 173568

__device__ __forceinline__ void mma_bf16(float d[4], const uint32_t a[4], uint32_t b0, uint32_t b1) {
    asm volatile("mma.sync.aligned.m16n8k16.row.col.f32.bf16.bf16.f32 "
        "{%0,%1,%2,%3}, {%4,%5,%6,%7}, {%8,%9}, {%0,%1,%2,%3};"
        : "+f"(d[0]), "+f"(d[1]), "+f"(d[2]), "+f"(d[3])
        : "r"(a[0]), "r"(a[1]), "r"(a[2]), "r"(a[3]), "r"(b0), "r"(b1));
}

// Weights [K][N] row-major -> fragment-major smem: per (frag,lane) 16B {bh0,bh1,bl0,bl1}
__device__ void conv_B(char* dsm, int off, const float* W, int N, int KT, int NT, int tid) {
    const int tot = KT * NT * 32;
    for (int idx = tid; idx < tot; idx += K2_THREADS) {
        const int l = idx & 31, frag = idx >> 5;
        const int nt = frag % NT, kt = frag / NT;
        const int k0 = kt * 16 + 2 * (l & 3), n = nt * 8 + (l >> 2);
        const float w00 = __ldg(W + k0 * N + n),       w01 = __ldg(W + (k0 + 1) * N + n);
        const float w10 = __ldg(W + (k0 + 8) * N + n), w11 = __ldg(W + (k0 + 9) * N + n);
        uint32_t h0, l0, h1, l1;
        split_pack(w00, w01, h0, l0);
        split_pack(w10, w11, h1, l1);
        *(uint4*)(dsm + off + (size_t)idx * 16) = make_uint4(h0, h1, l0, l1);
    }
}

// kt OUTER, nt INNER: consecutive MMAs hit different accumulators -> NT-way ILP.
template<int KT, int NT>
__device__ __forceinline__ void do_layer_ilp(const char* B, const float* bias,
        const uint32_t ah[][4], const uint32_t al[][4], float d[][4], int lane, int a2) {
    #pragma unroll
    for (int nt = 0; nt < NT; nt++) {
        const float b0 = bias[nt * 8 + a2], b1 = bias[nt * 8 + a2 + 1];
        d[nt][0] = b0; d[nt][1] = b1; d[nt][2] = b0; d[nt][3] = b1;
    }
    #pragma unroll
    for (int kt = 0; kt < KT; kt++) {
        #pragma unroll
        for (int nt = 0; nt < NT; nt++) {
            const uint4 q = *(const uint4*)(B + (size_t)((kt * NT + nt) * 32 + lane) * 16);
            mma_bf16(d[nt], ah[kt], q.x, q.y);
            mma_bf16(d[nt], ah[kt], q.z, q.w);
            mma_bf16(d[nt], al[kt], q.x, q.y);
        }
    }
}

template<int NT, bool LEAKY>
__device__ __forceinline__ void act_to_A(const float d[][4], uint32_t ah[][4], uint32_t al[][4]) {
    #pragma unroll
    for (int p = 0; p < NT / 2; p++) {
        #pragma unroll
        for (int h = 0; h < 2; h++) {
            const float* dd = d[2 * p + h];
            float x0, x1, x2, x3;
            if (LEAKY) { x0 = lrelu(dd[0]); x1 = lrelu(dd[1]); x2 = lrelu(dd[2]); x3 = lrelu(dd[3]); }
            else { x0 = fmaxf(dd[0], 0.f); x1 = fmaxf(dd[1], 0.f); x2 = fmaxf(dd[2], 0.f); x3 = fmaxf(dd[3], 0.f); }
            split_pack(x0, x1, ah[p][2 * h],     al[p][2 * h]);
            split_pack(x2, x3, ah[p][2 * h + 1], al[p][2 * h + 1]);
        }
    }
}

__global__ __launch_bounds__(K2_THREADS)
void mlp_kernel(
    const float* __restrict__ W_code, const float* __restrict__ b_code,
    const float* __restrict__ W_h1,   const float* __restrict__ b_h1,
    const float* __restrict__ W_h2,   const float* __restrict__ b_h2,
    const float* __restrict__ W_h3,   const float* __restrict__ b_h3,
    const float* __restrict__ W_h4,   const float* __restrict__ b_h4,
    float* __restrict__ out)
{
    extern __shared__ __align__(16) char dsm[];
    float* fb = (float*)dsm;   // bc[0..128) b1[128..192) b2[192..224) b3[224..240) b4[240..243) W4[244..292)
    const int tid = threadIdx.x, warp = tid >> 5, lane = tid & 31;

    if (tid < 128) fb[tid] = b_code[tid];
    if (tid < 64)  fb[128 + tid] = b_h1[tid];
    if (tid < 32)  fb[192 + tid] = b_h2[tid];
    if (tid < 16)  fb[224 + tid] = b_h3[tid];
    if (tid < 3)   fb[240 + tid] = b_h4[tid];
    if (tid < 48)  fb[244 + tid] = W_h4[tid];
    conv_B(dsm, OFF_B1, W_code, 128, 6, 16, tid);
    conv_B(dsm, OFF_B2, W_h1,    64, 8,  8, tid);
    conv_B(dsm, OFF_B3, W_h2,    32, 4,  4, tid);
    conv_B(dsm, OFF_B4, W_h3,    16, 2,  2, tid);
    __syncthreads();

    const int a2 = 2 * (lane & 3), rr = lane >> 2;
    float* vs = (float*)(dsm + OFF_VS + warp * VS_BYTES);   // [16 rows][104]

    for (int t = blockIdx.x * NW2 + warp; t < 2048; t += 148 * NW2) {
        // ---- stage v tile (16 rows x 96) from global, coalesced ----
        const float4* src = (const float4*)(g_v + (size_t)t * 1536);
        #pragma unroll
        for (int j = 0; j < 12; j++) {
            const int idx = lane + j * 32;                 // 0..383
            const int row = idx / 24, c4 = idx - row * 24;
            *(float4*)(vs + row * 104 + c4 * 4) = src[idx];
        }
        __syncwarp();

        // ---- A1 fragments ----
        uint32_t ah[8][4], al[8][4], ah2[8][4], al2[8][4];
        #pragma unroll
        for (int kt = 0; kt < 6; kt++) {
            const int k0 = kt * 16 + a2;
            float2 p0 = *(const float2*)(vs + rr * 104 + k0);
            float2 p1 = *(const float2*)(vs + (rr + 8) * 104 + k0);
            float2 p2 = *(const float2*)(vs + rr * 104 + k0 + 8);
            float2 p3 = *(const float2*)(vs + (rr + 8) * 104 + k0 + 8);
            split_pack(p0.x, p0.y, ah[kt][0], al[kt][0]);
            split_pack(p1.x, p1.y, ah[kt][1], al[kt][1]);
            split_pack(p2.x, p2.y, ah[kt][2], al[kt][2]);
            split_pack(p3.x, p3.y, ah[kt][3], al[kt][3]);
        }

        // ---- L1 (KT=6, NT=16) in two NT=8 halves; kt-outer/nt-inner inside each ----
        #pragma unroll
        for (int half = 0; half < 2; half++) {
            float d1[8][4];
            #pragma unroll
            for (int n8 = 0; n8 < 8; n8++) {
                const int nt = half * 8 + n8;
                const float b0 = fb[nt * 8 + a2], b1 = fb[nt * 8 + a2 + 1];
                d1[n8][0] = b0; d1[n8][1] = b1; d1[n8][2] = b0; d1[n8][3] = b1;
            }
            #pragma unroll
            for (int kt = 0; kt < 6; kt++) {
                #pragma unroll
                for (int n8 = 0; n8 < 8; n8++) {
                    const int nt = half * 8 + n8;
                    const uint4 q = *(const uint4*)(dsm + OFF_B1 + (size_t)((kt * 16 + nt) * 32 + lane) * 16);
                    mma_bf16(d1[n8], ah[kt], q.x, q.y);
                    mma_bf16(d1[n8], ah[kt], q.z, q.w);
                    mma_bf16(d1[n8], al[kt], q.x, q.y);
                }
            }
            #pragma unroll
            for (int p = 0; p < 4; p++) {
                const int kt2 = half * 4 + p;
                split_pack(lrelu(d1[2*p][0]),   lrelu(d1[2*p][1]),   ah2[kt2][0], al2[kt2][0]);
                split_pack(lrelu(d1[2*p][2]),   lrelu(d1[2*p][3]),   ah2[kt2][1], al2[kt2][1]);
                split_pack(lrelu(d1[2*p+1][0]), lrelu(d1[2*p+1][1]), ah2[kt2][2], al2[kt2][2]);
                split_pack(lrelu(d1[2*p+1][2]), lrelu(d1[2*p+1][3]), ah2[kt2][3], al2[kt2][3]);
            }
        }

        // ---- L2 (KT=8, NT=8) ----
        float d2[8][4];
        do_layer_ilp<8, 8>(dsm + OFF_B2, fb + 128, ah2, al2, d2, lane, a2);
        act_to_A<8, false>(d2, ah, al);
        // ---- L3 (KT=4, NT=4) ----
        float d3[4][4];
        do_layer_ilp<4, 4>(dsm + OFF_B3, fb + 192, ah, al, d3, lane, a2);
        act_to_A<4, false>(d3, ah2, al2);
        // ---- L4 (KT=2, NT=2) ----
        float d4[2][4];
        do_layer_ilp<2, 2>(dsm + OFF_B4, fb + 224, ah2, al2, d4, lane, a2);

        // ---- tail: h3(16) -> out(3), quad shuffle reduce ----
        float h30[4], h31[4];
        h30[0] = fmaxf(d4[0][0], 0.f); h30[1] = fmaxf(d4[0][1], 0.f);
        h30[2] = fmaxf(d4[1][0], 0.f); h30[3] = fmaxf(d4[1][1], 0.f);
        h31[0] = fmaxf(d4[0][2], 0.f); h31[1] = fmaxf(d4[0][3], 0.f);
        h31[2] = fmaxf(d4[1][2], 0.f); h31[3] = fmaxf(d4[1][3], 0.f);
        float s0[3], s1[3];
        #pragma unroll
        for (int c = 0; c < 3; c++) {
            const float w0 = fb[244 + a2 * 3 + c],       w1 = fb[244 + (a2 + 1) * 3 + c];
            const float w2 = fb[244 + (a2 + 8) * 3 + c], w3 = fb[244 + (a2 + 9) * 3 + c];
            float t0 = fmaf(h30[0], w0, fmaf(h30[1], w1, fmaf(h30[2], w2, h30[3] * w3)));
            float t1 = fmaf(h31[0], w0, fmaf(h31[1], w1, fmaf(h31[2], w2, h31[3] * w3)));
            t0 += __shfl_xor_sync(0xffffffffu, t0, 1);
            t0 += __shfl_xor_sync(0xffffffffu, t0, 2);
            t1 += __shfl_xor_sync(0xffffffffu, t1, 1);
            t1 += __shfl_xor_sync(0xffffffffu, t1, 2);
            s0[c] = t0 + fb[240 + c];
            s1[c] = t1 + fb[240 + c];
        }
        const int c = lane & 3;
        if (c < 3) {
            const float o0 = (c == 0) ? s0[0] : ((c == 1) ? s0[1] : s0[2]);
            const float o1 = (c == 0) ? s1[0] : ((c == 1) ? s1[1] : s1[2]);
            out[((size_t)t * 16 + rr) * 3 + c]     = o0;
            out[((size_t)t * 16 + rr + 8) * 3 + c] = o1;
        }
        __syncwarp();
    }
}

extern "C" void kernel_launch(void* const* d_in, const int* in_sizes, int n_in,
                              void* d_out, int out_size)
{
    const float* pgi    = (const float*)d_in[0];
    const float* W_lift = (const float*)d_in[1];
    const float* b_lift = (const float*)d_in[2];
    const float* W_code = (const float*)d_in[3];
    const float* b_code = (const float*)d_in[4];
    const float* W_h1   = (const float*)d_in[5];
    const float* b_h1   = (const float*)d_in[6];
    const float* W_h2   = (const float*)d_in[7];
    const float* b_h2   = (const float*)d_in[8];
    const float* W_h3   = (const float*)d_in[9];
    const float* b_h3   = (const float*)d_in[10];
    const float* W_h4   = (const float*)d_in[11];
    const float* b_h4   = (const float*)d_in[12];
    float* out = (float*)d_out;

    cudaFuncSetAttribute(mlp_kernel,
                         cudaFuncAttributeMaxDynamicSharedMemorySize, SMEM2_BYTES);

    // K1: 4096 groups, 1 warp each -> 512 CTAs x 256 (48KB static smem, 4 CTAs/SM)
    lift_kernel<<<512, 256>>>(pgi, W_lift, b_lift);
    // K2: 2048 16-row tiles over 148 CTAs x 12 warps
    mlp_kernel<<<148, K2_THREADS, SMEM2_BYTES>>>(
        W_code, b_code, W_h1, b_h1, W_h2, b_h2, W_h3, b_h3, W_h4, b_h4, out);
}

// round 14
// speedup vs baseline: 1.1471x; 1.1471x over previous
#include <cuda_runtime.h>
#include <cuda_bf16.h>
#include <cstdint>

typedef unsigned long long u64;

// v scratch: [32768 rows][96 features] fp32, standard order k = ring*32 + ch
__device__ float g_v[32768 * 96];

// ---------------- packed fp32 helpers ----------------
__device__ __forceinline__ u64 fma2(u64 a, u64 b, u64 c) {
    u64 d; asm("fma.rn.f32x2 %0, %1, %2, %3;" : "=l"(d) : "l"(a), "l"(b), "l"(c)); return d;
}
__device__ __forceinline__ u64 pack2(float x, float y) {
    u64 d; asm("mov.b64 %0, {%1, %2};" : "=l"(d) : "r"(__float_as_uint(x)), "r"(__float_as_uint(y))); return d;
}
__device__ __forceinline__ u64 splat2(float x) {
    u64 d; asm("mov.b64 %0, {%1, %1};" : "=l"(d) : "r"(__float_as_uint(x))); return d;
}
__device__ __forceinline__ void unpack2(u64 a, float& x, float& y) {
    unsigned lo, hi; asm("mov.b64 {%0, %1}, %2;" : "=r"(lo), "=r"(hi) : "l"(a));
    x = __uint_as_float(lo); y = __uint_as_float(hi);
}
__device__ __forceinline__ u64 max2(u64 a, u64 b) {
    float a0, a1, b0, b1; unpack2(a, a0, a1); unpack2(b, b0, b1);
    return pack2(fmaxf(a0, b0), fmaxf(a1, b1));
}
__device__ __forceinline__ float lrelu(float x) { return fmaxf(x, 0.2f * x); }

__device__ __forceinline__ void split_pack(float a, float b, uint32_t& hi, uint32_t& lo) {
    __nv_bfloat16 ha = __float2bfloat16(a), hb = __float2bfloat16(b);
    __nv_bfloat16 la = __float2bfloat16(a - __bfloat162float(ha));
    __nv_bfloat16 lb = __float2bfloat16(b - __bfloat162float(hb));
    hi = (uint32_t)__bfloat16_as_ushort(ha) | ((uint32_t)__bfloat16_as_ushort(hb) << 16);
    lo = (uint32_t)__bfloat16_as_ushort(la) | ((uint32_t)__bfloat16_as_ushort(lb) << 16);
}

// ================= Kernel 1: LIFT (unchanged, proven) =================
__global__ __launch_bounds__(256)
void lift_kernel(const float* __restrict__ pgi,
                 const float* __restrict__ W_lift, const float* __restrict__ b_lift)
{
    __shared__ __align__(16) float pts_s[8][1536];
    const int warp = threadIdx.x >> 5, lane = threadIdx.x & 31;
    const int group = blockIdx.x * 8 + warp;
    float* pts = pts_s[warp];
    const int ld3 = lane / 3, lm3 = lane - ld3 * 3;

    const u64 ww0 = splat2(__ldg(W_lift + lane));
    const u64 ww1 = splat2(__ldg(W_lift + 32 + lane));
    const u64 ww2 = splat2(__ldg(W_lift + 64 + lane));
    const u64 bbl = splat2(__ldg(b_lift + lane));

    const int grow = group * 8;
    const int b = grow >> 10, g = grow & 1023;
    const int gi = g >> 5, gj = g & 31;
    const float* base = pgi + ((size_t)b * 65536 + (size_t)(gi * 8) * 256 + (size_t)(gj * 8)) * 3;
    if (lane < 24) {
        #pragma unroll
        for (int q = 0; q < 8; q++) {
            const int P = q >> 1, s = q & 1;
            const float* bq = base + q * 24;
            #pragma unroll
            for (int gr = 0; gr < 8; gr++) {
                const float val = __ldcs(bq + (size_t)gr * 768 + lane);
                const int p = gr * 8 + ld3;
                int off;
                if (lm3 == 2) off = 1024 + P * 128 + p * 2 + s;
                else          off = P * 256 + p * 4 + lm3 * 2 + s;
                pts[off] = val;
            }
        }
    }
    __syncwarp();

    #pragma unroll
    for (int P = 0; P < 4; P++) {
        const float* XY = pts + P * 256;
        const float* Z  = pts + 1024 + P * 128;
        u64 mi = pack2(-3.0e38f, -3.0e38f), mt = mi, mo = mi;
        #pragma unroll
        for (int p = 0; p < 64; p += 2) {
            const ulonglong2 xyA = *(const ulonglong2*)(XY + p * 4);
            const ulonglong2 xyB = *(const ulonglong2*)(XY + p * 4 + 4);
            const ulonglong2 zz  = *(const ulonglong2*)(Z + p * 2);
            const u64 hA = fma2(xyA.x, ww0, fma2(xyA.y, ww1, fma2(zz.x, ww2, bbl)));
            const u64 hB = fma2(xyB.x, ww0, fma2(xyB.y, ww1, fma2(zz.y, ww2, bbl)));
            { const int r = p >> 3, c = p & 7, d = min(min(r, c), min(7 - r, 7 - c));
              if (d == 3) mi = max2(mi, hA); else if (d == 2) mt = max2(mt, hA); else mo = max2(mo, hA); }
            { const int r = (p + 1) >> 3, c = (p + 1) & 7, d = min(min(r, c), min(7 - r, 7 - c));
              if (d == 3) mi = max2(mi, hB); else if (d == 2) mt = max2(mt, hB); else mo = max2(mo, hB); }
        }
        const size_t rb = (size_t)(grow + P * 2) * 96;
        float x0, x1;
        unpack2(mi, x0, x1);
        g_v[rb + lane]      = lrelu(x0); g_v[rb + 96 + lane]      = lrelu(x1);
        unpack2(mt, x0, x1);
        g_v[rb + 32 + lane] = lrelu(x0); g_v[rb + 96 + 32 + lane] = lrelu(x1);
        unpack2(mo, x0, x1);
        g_v[rb + 64 + lane] = lrelu(x0); g_v[rb + 96 + 64 + lane] = lrelu(x1);
    }
}

// ================= Kernel 2: MLP — spill-free, one tile per warp =================
#define K2_THREADS 512
#define NW2 16
#define OFF_B1 1536      // 96 frags * 512B  (W_code 96x128: KT=6, NT=16)
#define OFF_B2 50688     // 64 frags         (W_h1 128x64: KT=8, NT=8)
#define OFF_B3 83456     // 16 frags         (W_h2 64x32:  KT=4, NT=4)
#define OFF_B4 91648     // 4 frags          (W_h3 32x16:  KT=2, NT=2)
#define OFF_AL 93696     // 16 warps x 2 ping-pong x 4096B lane-private lo-frag buffers
#define AL_BYTES 4096
#define SMEM2_BYTES (OFF_AL + NW2 * 2 * AL_BYTES)   // 224768

__device__ __forceinline__ void mma_bf16(float d[4], const uint32_t a[4], uint32_t b0, uint32_t b1) {
    asm volatile("mma.sync.aligned.m16n8k16.row.col.f32.bf16.bf16.f32 "
        "{%0,%1,%2,%3}, {%4,%5,%6,%7}, {%8,%9}, {%0,%1,%2,%3};"
        : "+f"(d[0]), "+f"(d[1]), "+f"(d[2]), "+f"(d[3])
        : "r"(a[0]), "r"(a[1]), "r"(a[2]), "r"(a[3]), "r"(b0), "r"(b1));
}

// Weights [K][N] row-major -> fragment-major smem: per (frag,lane) 16B {bh0,bh1,bl0,bl1}
__device__ void conv_B(char* dsm, int off, const float* W, int N, int KT, int NT, int tid) {
    const int tot = KT * NT * 32;
    for (int idx = tid; idx < tot; idx += K2_THREADS) {
        const int l = idx & 31, frag = idx >> 5;
        const int nt = frag % NT, kt = frag / NT;
        const int k0 = kt * 16 + 2 * (l & 3), n = nt * 8 + (l >> 2);
        const float w00 = __ldg(W + k0 * N + n),       w01 = __ldg(W + (k0 + 1) * N + n);
        const float w10 = __ldg(W + (k0 + 8) * N + n), w11 = __ldg(W + (k0 + 9) * N + n);
        uint32_t h0, l0, h1, l1;
        split_pack(w00, w01, h0, l0);
        split_pack(w10, w11, h1, l1);
        *(uint4*)(dsm + off + (size_t)idx * 16) = make_uint4(h0, h1, l0, l1);
    }
}

// A-lo streamed from lane-private smem (albuf pre-offset by lane*16); kt outer, nt inner.
template<int KT, int NT>
__device__ __forceinline__ void do_layer_sm(const char* B, const char* albuf, const float* bias,
        const uint32_t ah[][4], float d[][4], int lane, int a2) {
    #pragma unroll
    for (int nt = 0; nt < NT; nt++) {
        const float b0 = bias[nt * 8 + a2], b1 = bias[nt * 8 + a2 + 1];
        d[nt][0] = b0; d[nt][1] = b1; d[nt][2] = b0; d[nt][3] = b1;
    }
    #pragma unroll
    for (int kt = 0; kt < KT; kt++) {
        const uint4 av = *(const uint4*)(albuf + kt * 512);
        const uint32_t alr[4] = { av.x, av.y, av.z, av.w };
        #pragma unroll
        for (int nt = 0; nt < NT; nt++) {
            const uint4 q = *(const uint4*)(B + (size_t)((kt * NT + nt) * 32 + lane) * 16);
            mma_bf16(d[nt], ah[kt], q.x, q.y);
            mma_bf16(d[nt], ah[kt], q.z, q.w);
            mma_bf16(d[nt], alr,    q.x, q.y);
        }
    }
}

// activation -> next A frags: hi to regs, lo to lane-private smem buffer
template<int NT, bool LEAKY>
__device__ __forceinline__ void act_sm(const float d[][4], uint32_t ah[][4], char* albuf_out) {
    #pragma unroll
    for (int p = 0; p < NT / 2; p++) {
        float x[8];
        #pragma unroll
        for (int h = 0; h < 2; h++) {
            const float* dd = d[2 * p + h];
            #pragma unroll
            for (int e = 0; e < 4; e++)
                x[h * 4 + e] = LEAKY ? lrelu(dd[e]) : fmaxf(dd[e], 0.f);
        }
        uint32_t lo[4];
        split_pack(x[0], x[1], ah[p][0], lo[0]);
        split_pack(x[2], x[3], ah[p][1], lo[1]);
        split_pack(x[4], x[5], ah[p][2], lo[2]);
        split_pack(x[6], x[7], ah[p][3], lo[3]);
        *(uint4*)(albuf_out + p * 512) = make_uint4(lo[0], lo[1], lo[2], lo[3]);
    }
}

__global__ __launch_bounds__(K2_THREADS, 1)
void mlp_kernel(
    const float* __restrict__ W_code, const float* __restrict__ b_code,
    const float* __restrict__ W_h1,   const float* __restrict__ b_h1,
    const float* __restrict__ W_h2,   const float* __restrict__ b_h2,
    const float* __restrict__ W_h3,   const float* __restrict__ b_h3,
    const float* __restrict__ W_h4,   const float* __restrict__ b_h4,
    float* __restrict__ out)
{
    extern __shared__ __align__(16) char dsm[];
    float* fb = (float*)dsm;   // bc[0..128) b1[128..192) b2[192..224) b3[224..240) b4[240..243) W4[244..292)
    const int tid = threadIdx.x, warp = tid >> 5, lane = tid & 31;

    if (tid < 128) fb[tid] = b_code[tid];
    if (tid < 64)  fb[128 + tid] = b_h1[tid];
    if (tid < 32)  fb[192 + tid] = b_h2[tid];
    if (tid < 16)  fb[224 + tid] = b_h3[tid];
    if (tid < 3)   fb[240 + tid] = b_h4[tid];
    if (tid < 48)  fb[244 + tid] = W_h4[tid];
    conv_B(dsm, OFF_B1, W_code, 128, 6, 16, tid);
    conv_B(dsm, OFF_B2, W_h1,    64, 8,  8, tid);
    conv_B(dsm, OFF_B3, W_h2,    32, 4,  4, tid);
    conv_B(dsm, OFF_B4, W_h3,    16, 2,  2, tid);
    __syncthreads();

    const int a2 = 2 * (lane & 3), rr = lane >> 2;
    const int t = blockIdx.x * NW2 + warp;     // exactly one 16-row tile per warp (grid=128)
    // lane-private lo-fragment buffers (each thread touches only its own 16B slots)
    char* al0 = dsm + OFF_AL + (size_t)(warp * 2 + 0) * AL_BYTES + lane * 16;
    char* al1 = dsm + OFF_AL + (size_t)(warp * 2 + 1) * AL_BYTES + lane * 16;

    // ---- A1 fragments straight from L2-resident g_v ----
    uint32_t ah[8][4], ah2[8][4];
    {
        const float* vr0 = g_v + (size_t)(t * 16 + rr) * 96;
        const float* vr8 = vr0 + 8 * 96;
        #pragma unroll
        for (int kt = 0; kt < 6; kt++) {
            const int k0 = kt * 16 + a2;
            const float2 p0 = *(const float2*)(vr0 + k0);
            const float2 p1 = *(const float2*)(vr8 + k0);
            const float2 p2 = *(const float2*)(vr0 + k0 + 8);
            const float2 p3 = *(const float2*)(vr8 + k0 + 8);
            uint32_t lo[4];
            split_pack(p0.x, p0.y, ah[kt][0], lo[0]);
            split_pack(p1.x, p1.y, ah[kt][1], lo[1]);
            split_pack(p2.x, p2.y, ah[kt][2], lo[2]);
            split_pack(p3.x, p3.y, ah[kt][3], lo[3]);
            *(uint4*)(al0 + kt * 512) = make_uint4(lo[0], lo[1], lo[2], lo[3]);
        }
    }

    // ---- L1 (KT=6, NT=16) in two NT=8 halves; reads al0, writes al1 ----
    #pragma unroll
    for (int half = 0; half < 2; half++) {
        float d1[8][4];
        #pragma unroll
        for (int n8 = 0; n8 < 8; n8++) {
            const int nt = half * 8 + n8;
            const float b0 = fb[nt * 8 + a2], b1 = fb[nt * 8 + a2 + 1];
            d1[n8][0] = b0; d1[n8][1] = b1; d1[n8][2] = b0; d1[n8][3] = b1;
        }
        #pragma unroll
        for (int kt = 0; kt < 6; kt++) {
            const uint4 av = *(const uint4*)(al0 + kt * 512);
            const uint32_t alr[4] = { av.x, av.y, av.z, av.w };
            #pragma unroll
            for (int n8 = 0; n8 < 8; n8++) {
                const int nt = half * 8 + n8;
                const uint4 q = *(const uint4*)(dsm + OFF_B1 + (size_t)((kt * 16 + nt) * 32 + lane) * 16);
                mma_bf16(d1[n8], ah[kt], q.x, q.y);
                mma_bf16(d1[n8], ah[kt], q.z, q.w);
                mma_bf16(d1[n8], alr,    q.x, q.y);
            }
        }
        #pragma unroll
        for (int p = 0; p < 4; p++) {
            const int kt2 = half * 4 + p;
            float x[8];
            #pragma unroll
            for (int h = 0; h < 2; h++)
                #pragma unroll
                for (int e = 0; e < 4; e++)
                    x[h * 4 + e] = lrelu(d1[2 * p + h][e]);
            uint32_t lo[4];
            split_pack(x[0], x[1], ah2[kt2][0], lo[0]);
            split_pack(x[2], x[3], ah2[kt2][1], lo[1]);
            split_pack(x[4], x[5], ah2[kt2][2], lo[2]);
            split_pack(x[6], x[7], ah2[kt2][3], lo[3]);
            *(uint4*)(al1 + kt2 * 512) = make_uint4(lo[0], lo[1], lo[2], lo[3]);
        }
    }

    // ---- L2 (KT=8, NT=8): reads ah2+al1, writes ah+al0 ----
    float d2[8][4];
    do_layer_sm<8, 8>(dsm + OFF_B2, al1, fb + 128, ah2, d2, lane, a2);
    act_sm<8, false>(d2, ah, al0);
    // ---- L3 (KT=4, NT=4): reads ah+al0, writes ah2+al1 ----
    float d3[4][4];
    do_layer_sm<4, 4>(dsm + OFF_B3, al0, fb + 192, ah, d3, lane, a2);
    act_sm<4, false>(d3, ah2, al1);
    // ---- L4 (KT=2, NT=2) ----
    float d4[2][4];
    do_layer_sm<2, 2>(dsm + OFF_B4, al1, fb + 224, ah2, d4, lane, a2);

    // ---- tail: h3(16) -> out(3), quad shuffle reduce ----
    float h30[4], h31[4];
    h30[0] = fmaxf(d4[0][0], 0.f); h30[1] = fmaxf(d4[0][1], 0.f);
    h30[2] = fmaxf(d4[1][0], 0.f); h30[3] = fmaxf(d4[1][1], 0.f);
    h31[0] = fmaxf(d4[0][2], 0.f); h31[1] = fmaxf(d4[0][3], 0.f);
    h31[2] = fmaxf(d4[1][2], 0.f); h31[3] = fmaxf(d4[1][3], 0.f);
    float s0[3], s1[3];
    #pragma unroll
    for (int c = 0; c < 3; c++) {
        const float w0 = fb[244 + a2 * 3 + c],       w1 = fb[244 + (a2 + 1) * 3 + c];
        const float w2 = fb[244 + (a2 + 8) * 3 + c], w3 = fb[244 + (a2 + 9) * 3 + c];
        float t0 = fmaf(h30[0], w0, fmaf(h30[1], w1, fmaf(h30[2], w2, h30[3] * w3)));
        float t1 = fmaf(h31[0], w0, fmaf(h31[1], w1, fmaf(h31[2], w2, h31[3] * w3)));
        t0 += __shfl_xor_sync(0xffffffffu, t0, 1);
        t0 += __shfl_xor_sync(0xffffffffu, t0, 2);
        t1 += __shfl_xor_sync(0xffffffffu, t1, 1);
        t1 += __shfl_xor_sync(0xffffffffu, t1, 2);
        s0[c] = t0 + fb[240 + c];
        s1[c] = t1 + fb[240 + c];
    }
    const int c = lane & 3;
    if (c < 3) {
        const float o0 = (c == 0) ? s0[0] : ((c == 1) ? s0[1] : s0[2]);
        const float o1 = (c == 0) ? s1[0] : ((c == 1) ? s1[1] : s1[2]);
        out[((size_t)t * 16 + rr) * 3 + c]     = o0;
        out[((size_t)t * 16 + rr + 8) * 3 + c] = o1;
    }
}

extern "C" void kernel_launch(void* const* d_in, const int* in_sizes, int n_in,
                              void* d_out, int out_size)
{
    const float* pgi    = (const float*)d_in[0];
    const float* W_lift = (const float*)d_in[1];
    const float* b_lift = (const float*)d_in[2];
    const float* W_code = (const float*)d_in[3];
    const float* b_code = (const float*)d_in[4];
    const float* W_h1   = (const float*)d_in[5];
    const float* b_h1   = (const float*)d_in[6];
    const float* W_h2   = (const float*)d_in[7];
    const float* b_h2   = (const float*)d_in[8];
    const float* W_h3   = (const float*)d_in[9];
    const float* b_h3   = (const float*)d_in[10];
    const float* W_h4   = (const float*)d_in[11];
    const float* b_h4   = (const float*)d_in[12];
    float* out = (float*)d_out;

    cudaFuncSetAttribute(mlp_kernel,
                         cudaFuncAttributeMaxDynamicSharedMemorySize, SMEM2_BYTES);

    // K1: 4096 groups, 1 warp each -> 512 CTAs x 256
    lift_kernel<<<512, 256>>>(pgi, W_lift, b_lift);
    // K2: 128 CTAs x 16 warps = 2048 warps, exactly one 16-row tile each
    mlp_kernel<<<128, K2_THREADS, SMEM2_BYTES>>>(
        W_code, b_code, W_h1, b_h1, W_h2, b_h2, W_h3, b_h3, W_h4, b_h4, out);
}